// round 13
// baseline (speedup 1.0000x reference)
#include <cuda_runtime.h>
#include <cuda_bf16.h>
#include <math.h>
#include <stdint.h>

// ---------------- problem constants ----------------
static constexpr int TOKENS = 100352;          // B*L
static constexpr long QKV_STRIDE = 19267584L;  // TOKENS*192
static constexpr float QSCALE = 0.17677669529663687f; // 32^-0.5

// ---------------- scratch (device globals; no allocation) ----------------
__device__ __nv_bfloat16 g_a_bf[19267584];    // LN1 out (window order) -> reused as attn out
__device__ __nv_bfloat16 g_qkv_bf[57802752];  // qkv ; first third reused as LN2 out
__device__ float         g_x[19267584];       // x after attention residual (fp32)
__device__ __nv_bfloat16 g_h_bf[77070336];    // fc1/gelu output (TOKENS*768)
__device__ __nv_bfloat16 g_w_bf[442368];      // bf16 weights row-major [K,N]: qkv|proj|fc1|fc2
__device__ __nv_bfloat16 g_bm[75264];         // bias+mask bf16: 4 wtypes x 6 heads x 49 x 64

// ---------------- prep: weight convert + padded bf16 bias/mask table ----------------
__global__ void prep_kernel(const float* __restrict__ w0, const float* __restrict__ w1,
                            const float* __restrict__ w2, const float* __restrict__ w3,
                            __nv_bfloat16* __restrict__ d,
                            const float* __restrict__ table, __nv_bfloat16* __restrict__ bm) {
    if (blockIdx.x < 1728) {
        int i = blockIdx.x * 256 + threadIdx.x;
        if (i >= 442368) return;
        float v;
        if (i < 110592) v = w0[i];
        else if (i < 147456) v = w1[i - 110592];
        else if (i < 294912) v = w2[i - 147456];
        else v = w3[i - 294912];
        d[i] = __float2bfloat16(v);
    } else {
        int th = blockIdx.x - 1728;
        int typ = th / 6, h = th - typ * 6;
        int wrow = (typ & 2) ? 49 : 0, wcol = (typ & 1) ? 49 : 0;
        for (int e = threadIdx.x; e < 49 * 64; e += 256) {
            int n = e >> 6, m = e & 63;
            float v;
            if (m < 49) {
                int ni = n / 7, nj = n - ni * 7, mi = m / 7, mj = m - mi * 7;
                v = table[((ni - mi + 6) * 13 + (nj - mj + 6)) * 6 + h];
                int rn = wrow + ni, cn = wcol + nj, rm = wrow + mi, cm = wcol + mj;
                int idn = (rn < 49 ? 0 : (rn < 53 ? 1 : 2)) * 3 + (cn < 49 ? 0 : (cn < 53 ? 1 : 2));
                int idm = (rm < 49 ? 0 : (rm < 53 ? 1 : 2)) * 3 + (cm < 49 ? 0 : (cm < 53 ? 1 : 2));
                if (idn != idm) v -= 100.0f;
            } else {
                v = -1e9f;
            }
            bm[th * (49 * 64) + e] = __float2bfloat16(v);
        }
    }
}

// ---------------- LayerNorm (LN1 only now), warp-per-row ----------------
template<bool REMAP>
__global__ void __launch_bounds__(256)
ln_kernel(const float* __restrict__ x, const float* __restrict__ gamma,
          const float* __restrict__ beta, __nv_bfloat16* __restrict__ out) {
    const int warp = threadIdx.x >> 5, lane = threadIdx.x & 31;
    const int g = blockIdx.x * 8 + warp;
    long src;
    if (REMAP) {
        int gw = g / 49, n = g - gw * 49;
        int b = gw >> 6, wloc = gw & 63;
        int hp = (wloc >> 3) * 7 + n / 7;
        int wp = (wloc & 7) * 7 + n % 7;
        int hh = hp + 3; if (hh >= 56) hh -= 56;
        int ww = wp + 3; if (ww >= 56) ww -= 56;
        src = ((long)b * 3136 + hh * 56 + ww) * 192;
    } else {
        src = (long)g * 192;
    }
    float2 v[3];
    float s1 = 0.f, s2 = 0.f;
    #pragma unroll
    for (int i = 0; i < 3; i++) {
        v[i] = *(const float2*)&x[src + i * 64 + lane * 2];
        s1 += v[i].x + v[i].y;
        s2 += v[i].x * v[i].x + v[i].y * v[i].y;
    }
    #pragma unroll
    for (int o = 16; o; o >>= 1) {
        s1 += __shfl_xor_sync(0xffffffffu, s1, o);
        s2 += __shfl_xor_sync(0xffffffffu, s2, o);
    }
    float mean = s1 * (1.f / 192.f);
    float var = s2 * (1.f / 192.f) - mean * mean;
    float rstd = rsqrtf(var + 1e-3f);
    #pragma unroll
    for (int i = 0; i < 3; i++) {
        int c = i * 64 + lane * 2;
        float2 gm = *(const float2*)&gamma[c];
        float2 bt = *(const float2*)&beta[c];
        __nv_bfloat162 p = __float22bfloat162_rn(make_float2(
            (v[i].x - mean) * rstd * gm.x + bt.x,
            (v[i].y - mean) * rstd * gm.y + bt.y));
        *(__nv_bfloat162*)&out[(long)g * 192 + c] = p;
    }
}

// ---------------- mma / ldmatrix helpers ----------------
__device__ __forceinline__ void cpa16(void* sm, const void* gm) {
    uint32_t sa = (uint32_t)__cvta_generic_to_shared(sm);
    asm volatile("cp.async.cg.shared.global [%0], [%1], 16;" :: "r"(sa), "l"(gm));
}
__device__ __forceinline__ void mma_bf16(float* d, const uint32_t* a, const uint32_t* b) {
    asm volatile(
        "mma.sync.aligned.m16n8k16.row.col.f32.bf16.bf16.f32 "
        "{%0,%1,%2,%3}, {%4,%5,%6,%7}, {%8,%9}, {%0,%1,%2,%3};"
        : "+f"(d[0]), "+f"(d[1]), "+f"(d[2]), "+f"(d[3])
        : "r"(a[0]), "r"(a[1]), "r"(a[2]), "r"(a[3]), "r"(b[0]), "r"(b[1]));
}
__device__ __forceinline__ void ldm_x4(uint32_t* r, const void* p) {
    uint32_t sa = (uint32_t)__cvta_generic_to_shared(p);
    asm volatile("ldmatrix.sync.aligned.m8n8.x4.shared.b16 {%0,%1,%2,%3}, [%4];"
                 : "=r"(r[0]), "=r"(r[1]), "=r"(r[2]), "=r"(r[3]) : "r"(sa));
}
__device__ __forceinline__ void ldm_x4t(uint32_t* r, const void* p) {
    uint32_t sa = (uint32_t)__cvta_generic_to_shared(p);
    asm volatile("ldmatrix.sync.aligned.m8n8.x4.trans.shared.b16 {%0,%1,%2,%3}, [%4];"
                 : "=r"(r[0]), "=r"(r[1]), "=r"(r[2]), "=r"(r[3]) : "r"(sa));
}

// ---------------- shared GEMM epilogue (QKV/GELU/RES) ----------------
enum { EPI_QKV = 0, EPI_GELU = 2, EPI_RES = 3 };

template<int EPI>
__device__ __forceinline__ void gemm_epilogue(
    float acc[2][6][4], int bm, int bn, int wm, int wn, int lane,
    const float* __restrict__ bias, void* __restrict__ outv,
    const float* __restrict__ res, int N) {
    const int g = lane >> 2, t = lane & 3;
    #pragma unroll
    for (int mt = 0; mt < 2; ++mt)
        #pragma unroll
        for (int rr = 0; rr < 2; ++rr) {
            const int row = bm + wm * 32 + mt * 16 + rr * 8 + g;
            int win = 0, n = 0;
            if (EPI == EPI_QKV) { win = row / 49; n = row - win * 49; }
            #pragma unroll
            for (int nt = 0; nt < 6; ++nt) {
                const int col = bn + wn * 48 + nt * 8 + t * 2;
                float v0 = acc[mt][nt][rr * 2 + 0] + bias[col];
                float v1 = acc[mt][nt][rr * 2 + 1] + bias[col + 1];
                if (EPI == EPI_QKV) {
                    int which = col / 192;
                    int rem = col - which * 192;
                    int h = rem >> 5, d = rem & 31;
                    if (which == 0) { v0 *= QSCALE; v1 *= QSCALE; }
                    __nv_bfloat162 p = __float22bfloat162_rn(make_float2(v0, v1));
                    *(__nv_bfloat162*)&((__nv_bfloat16*)outv)[(long)which * QKV_STRIDE +
                        (((long)win * 6 + h) * 49 + n) * 32 + d] = p;
                } else if (EPI == EPI_GELU) {
                    float u0 = 0.7978845608028654f * (v0 + 0.044715f * v0 * v0 * v0);
                    float u1 = 0.7978845608028654f * (v1 + 0.044715f * v1 * v1 * v1);
                    float t0, t1;
                    asm("tanh.approx.f32 %0, %1;" : "=f"(t0) : "f"(u0));
                    asm("tanh.approx.f32 %0, %1;" : "=f"(t1) : "f"(u1));
                    __nv_bfloat162 p = __float22bfloat162_rn(
                        make_float2(0.5f * v0 * (1.f + t0), 0.5f * v1 * (1.f + t1)));
                    *(__nv_bfloat162*)&((__nv_bfloat16*)outv)[(long)row * N + col] = p;
                } else {  // EPI_RES
                    long idx2 = (long)row * N + col;
                    float2 r2 = *(const float2*)&res[idx2];
                    *(float2*)&((float*)outv)[idx2] = make_float2(r2.x + v0, r2.y + v1);
                }
            }
        }
}

// ---------------- full-K-resident GEMM (K=192), chunked-load overlap ----------------
template<int EPI>
__global__ void __launch_bounds__(256, 2)
gemm_fullk(const __nv_bfloat16* __restrict__ A, const __nv_bfloat16* __restrict__ W,
           const float* __restrict__ bias, void* __restrict__ outv,
           const float* __restrict__ res, int M, int N) {
    extern __shared__ __align__(16) __nv_bfloat16 smem[];
    __nv_bfloat16* sA = smem;               // 128 x 192
    __nv_bfloat16* sB = smem + 128 * 192;   // 192 x 128 (96 used)
    const int tid = threadIdx.x, lane = tid & 31, warp = tid >> 5;
    const int wm = warp >> 1, wn = warp & 1;
    const int bm = blockIdx.y * 128, bn = blockIdx.x * 96;

    #pragma unroll
    for (int gch = 0; gch < 3; ++gch) {
        #pragma unroll
        for (int i = 0; i < 4; i++) {
            int idx = i * 256 + tid, r = idx >> 3, cc = idx & 7;
            cpa16(&sA[r * 192 + gch * 64 + ((cc ^ (r & 7)) << 3)],
                  A + (long)(bm + r) * 192 + gch * 64 + cc * 8);
        }
        #pragma unroll
        for (int i = 0; i < 3; i++) {
            int idx = i * 256 + tid, rl = idx / 12, c = idx % 12;
            int r = gch * 64 + rl;
            cpa16(&sB[r * 128 + (((c & 8) | ((c & 7) ^ (r & 7))) << 3)],
                  W + (long)r * N + bn + c * 8);
        }
        asm volatile("cp.async.commit_group;");
    }

    float acc[2][6][4];
    #pragma unroll
    for (int i = 0; i < 2; i++)
        #pragma unroll
        for (int j = 0; j < 6; j++)
            #pragma unroll
            for (int e = 0; e < 4; e++) acc[i][j][e] = 0.f;

    #pragma unroll
    for (int gch = 0; gch < 3; ++gch) {
        if (gch == 0)      asm volatile("cp.async.wait_group 2;");
        else if (gch == 1) asm volatile("cp.async.wait_group 1;");
        else               asm volatile("cp.async.wait_group 0;");
        __syncthreads();
        #pragma unroll
        for (int kk = 0; kk < 4; ++kk) {
            const int ks = gch * 4 + kk;
            uint32_t af[2][4], bfr[3][4];
            #pragma unroll
            for (int mt = 0; mt < 2; ++mt) {
                int mrow = wm * 32 + mt * 16 + (lane & 15);
                int c = (ks << 1) + (lane >> 4);
                ldm_x4(af[mt], &sA[mrow * 192 + (c >> 3) * 64 + (((c & 7) ^ (mrow & 7)) << 3)]);
            }
            #pragma unroll
            for (int ng = 0; ng < 3; ++ng) {
                int krow = (ks << 4) + (lane & 7) + ((lane >> 3) & 1) * 8;
                int nc = wn * 6 + ng * 2 + (lane >> 4);
                int sw = (nc & 8) | ((nc & 7) ^ (krow & 7));
                ldm_x4t(bfr[ng], &sB[krow * 128 + (sw << 3)]);
            }
            #pragma unroll
            for (int mt = 0; mt < 2; ++mt)
                #pragma unroll
                for (int ng = 0; ng < 3; ++ng) {
                    mma_bf16(acc[mt][ng * 2 + 0], af[mt], &bfr[ng][0]);
                    mma_bf16(acc[mt][ng * 2 + 1], af[mt], &bfr[ng][2]);
                }
        }
    }
    gemm_epilogue<EPI>(acc, bm, bn, wm, wn, lane, bias, outv, res, N);
}

// ---------------- fused proj + residual + LN2 : BM=128, BN=192, 512 threads ----------------
__global__ void __launch_bounds__(512, 1)
gemm_proj_ln(const __nv_bfloat16* __restrict__ A, const __nv_bfloat16* __restrict__ W,
             const float* __restrict__ bias, float* __restrict__ xr,
             const float* __restrict__ res,
             const float* __restrict__ gamma2, const float* __restrict__ beta2,
             __nv_bfloat16* __restrict__ ln2out) {
    extern __shared__ __align__(16) __nv_bfloat16 smem[];
    __nv_bfloat16* sA = smem;                       // 128 x 192  (49152 B)
    __nv_bfloat16* sB = smem + 128 * 192;           // 192 x 192  (73728 B)
    float* red = (float*)(smem + 128 * 192 + 192 * 192);  // [2][128][4] = 4096 B
    const int tid = threadIdx.x, lane = tid & 31, warp = tid >> 5;
    const int wm = warp >> 2, wn = warp & 3;        // 4 x 4 warps, warp tile 32x48
    const int bm = blockIdx.x * 128;

    // chunked loads: 3 groups over K
    #pragma unroll
    for (int gch = 0; gch < 3; ++gch) {
        #pragma unroll
        for (int i = 0; i < 2; i++) {
            int idx = i * 512 + tid, r = idx >> 3, cc = idx & 7;
            cpa16(&sA[r * 192 + gch * 64 + ((cc ^ (r & 7)) << 3)],
                  A + (long)(bm + r) * 192 + gch * 64 + cc * 8);
        }
        #pragma unroll
        for (int i = 0; i < 3; i++) {
            int idx = i * 512 + tid, rl = idx / 24, c = idx % 24;
            int r = gch * 64 + rl;
            cpa16(&sB[r * 192 + (((c & 24) | ((c & 7) ^ (r & 7))) << 3)],
                  W + (long)r * 192 + c * 8);
        }
        asm volatile("cp.async.commit_group;");
    }

    float acc[2][6][4];
    #pragma unroll
    for (int i = 0; i < 2; i++)
        #pragma unroll
        for (int j = 0; j < 6; j++)
            #pragma unroll
            for (int e = 0; e < 4; e++) acc[i][j][e] = 0.f;

    #pragma unroll
    for (int gch = 0; gch < 3; ++gch) {
        if (gch == 0)      asm volatile("cp.async.wait_group 2;");
        else if (gch == 1) asm volatile("cp.async.wait_group 1;");
        else               asm volatile("cp.async.wait_group 0;");
        __syncthreads();
        #pragma unroll
        for (int kk = 0; kk < 4; ++kk) {
            const int ks = gch * 4 + kk;
            uint32_t af[2][4], bfr[3][4];
            #pragma unroll
            for (int mt = 0; mt < 2; ++mt) {
                int mrow = wm * 32 + mt * 16 + (lane & 15);
                int c = (ks << 1) + (lane >> 4);
                ldm_x4(af[mt], &sA[mrow * 192 + (c >> 3) * 64 + (((c & 7) ^ (mrow & 7)) << 3)]);
            }
            #pragma unroll
            for (int ng = 0; ng < 3; ++ng) {
                int krow = (ks << 4) + (lane & 7) + ((lane >> 3) & 1) * 8;
                int nc = wn * 6 + ng * 2 + (lane >> 4);
                int sw = (nc & 24) | ((nc & 7) ^ (krow & 7));
                ldm_x4t(bfr[ng], &sB[krow * 192 + (sw << 3)]);
            }
            #pragma unroll
            for (int mt = 0; mt < 2; ++mt)
                #pragma unroll
                for (int ng = 0; ng < 3; ++ng) {
                    mma_bf16(acc[mt][ng * 2 + 0], af[mt], &bfr[ng][0]);
                    mma_bf16(acc[mt][ng * 2 + 1], af[mt], &bfr[ng][2]);
                }
        }
    }

    // ---- epilogue: xr = res + proj ; per-row LN2 ----
    const int g = lane >> 2, t = lane & 3;
    long tmap[2][2];
    float ps1[2][2], ps2[2][2];
    #pragma unroll
    for (int mt = 0; mt < 2; ++mt)
        #pragma unroll
        for (int rr = 0; rr < 2; ++rr) {
            const int row = bm + wm * 32 + mt * 16 + rr * 8 + g;
            int win = row / 49, n = row - win * 49;
            int b = win >> 6, wloc = win & 63;
            int hp = (wloc >> 3) * 7 + n / 7, wp = (wloc & 7) * 7 + n % 7;
            int hh = hp + 3; if (hh >= 56) hh -= 56;
            int ww = wp + 3; if (ww >= 56) ww -= 56;
            tmap[mt][rr] = ((long)b * 3136 + hh * 56 + ww) * 192;
            float s1 = 0.f, s2 = 0.f;
            #pragma unroll
            for (int nt = 0; nt < 6; ++nt) {
                const int col = wn * 48 + nt * 8 + t * 2;
                long ti = tmap[mt][rr] + col;
                float2 r2 = *(const float2*)&res[ti];
                float v0 = acc[mt][nt][rr * 2 + 0] + bias[col] + r2.x;
                float v1 = acc[mt][nt][rr * 2 + 1] + bias[col + 1] + r2.y;
                acc[mt][nt][rr * 2 + 0] = v0;
                acc[mt][nt][rr * 2 + 1] = v1;
                s1 += v0 + v1;
                s2 += v0 * v0 + v1 * v1;
            }
            // reduce over t (lane bits 0,1)
            s1 += __shfl_xor_sync(0xffffffffu, s1, 1);
            s2 += __shfl_xor_sync(0xffffffffu, s2, 1);
            s1 += __shfl_xor_sync(0xffffffffu, s1, 2);
            s2 += __shfl_xor_sync(0xffffffffu, s2, 2);
            ps1[mt][rr] = s1;
            ps2[mt][rr] = s2;
            if (t == 0) {
                int rl = wm * 32 + mt * 16 + rr * 8 + g;
                red[rl * 4 + wn] = s1;
                red[512 + rl * 4 + wn] = s2;
            }
        }
    __syncthreads();
    #pragma unroll
    for (int mt = 0; mt < 2; ++mt)
        #pragma unroll
        for (int rr = 0; rr < 2; ++rr) {
            const int rl = wm * 32 + mt * 16 + rr * 8 + g;
            float s1 = red[rl * 4 + 0] + red[rl * 4 + 1] + red[rl * 4 + 2] + red[rl * 4 + 3];
            float s2 = red[512 + rl * 4 + 0] + red[512 + rl * 4 + 1] +
                       red[512 + rl * 4 + 2] + red[512 + rl * 4 + 3];
            float mean = s1 * (1.f / 192.f);
            float var = s2 * (1.f / 192.f) - mean * mean;
            float rstd = rsqrtf(var + 1e-3f);
            #pragma unroll
            for (int nt = 0; nt < 6; ++nt) {
                const int col = wn * 48 + nt * 8 + t * 2;
                long ti = tmap[mt][rr] + col;
                float v0 = acc[mt][nt][rr * 2 + 0];
                float v1 = acc[mt][nt][rr * 2 + 1];
                *(float2*)&xr[ti] = make_float2(v0, v1);
                float2 gm = *(const float2*)&gamma2[col];
                float2 bt = *(const float2*)&beta2[col];
                __nv_bfloat162 p = __float22bfloat162_rn(make_float2(
                    (v0 - mean) * rstd * gm.x + bt.x,
                    (v1 - mean) * rstd * gm.y + bt.y));
                *(__nv_bfloat162*)&ln2out[ti] = p;
            }
        }
}

// ---------------- pipelined GEMM (K=768, FC2): 3-stage ----------------
template<int EPI>
__global__ void __launch_bounds__(256, 2)
gemm_bf16(const __nv_bfloat16* __restrict__ A, const __nv_bfloat16* __restrict__ W,
          const float* __restrict__ bias, void* __restrict__ outv,
          const float* __restrict__ res, int M, int N, int K) {
    extern __shared__ __align__(16) __nv_bfloat16 smem[];
    const int tid = threadIdx.x, lane = tid & 31, warp = tid >> 5;
    const int wm = warp >> 1, wn = warp & 1;
    const int bm = blockIdx.y * 128, bn = blockIdx.x * 96;

    float acc[2][6][4];
    #pragma unroll
    for (int i = 0; i < 2; i++)
        #pragma unroll
        for (int j = 0; j < 6; j++)
            #pragma unroll
            for (int e = 0; e < 4; e++) acc[i][j][e] = 0.f;

    const int nstages = K >> 6;   // 12

    #define LOAD_STAGE(s, k0)                                                          \
        {                                                                              \
            __nv_bfloat16* sa = smem + (s) * 16384;                                    \
            __nv_bfloat16* sb = sa + 8192;                                             \
            _Pragma("unroll")                                                          \
            for (int i = 0; i < 4; i++) {                                              \
                int idx = tid + i * 256, row = idx >> 3, c = idx & 7;                  \
                cpa16(&sa[(row << 6) + ((c ^ (row & 7)) << 3)],                        \
                      A + (long)(bm + row) * K + (k0) + (c << 3));                     \
            }                                                                          \
            _Pragma("unroll")                                                          \
            for (int i = 0; i < 4; i++) {                                              \
                int idx = tid + i * 256, row = idx >> 4, c = idx & 15;                 \
                if (c < 12)                                                            \
                    cpa16(&sb[(row << 7) + (((c & 8) | ((c & 7) ^ (row & 7))) << 3)],  \
                          W + (long)((k0) + row) * N + bn + (c << 3));                 \
            }                                                                          \
            asm volatile("cp.async.commit_group;");                                    \
        }

    LOAD_STAGE(0, 0)
    LOAD_STAGE(1, 64)

    for (int it = 0; it < nstages; ++it) {
        if (it + 2 < nstages) {
            asm volatile("cp.async.wait_group 1;");
        } else {
            asm volatile("cp.async.wait_group 0;");
        }
        __syncthreads();
        if (it + 2 < nstages) {
            int s2 = (it + 2) % 3;
            LOAD_STAGE(s2, (it + 2) << 6)
        }
        const __nv_bfloat16* sa = smem + (it % 3) * 16384;
        const __nv_bfloat16* sb = sa + 8192;
        #pragma unroll
        for (int ks = 0; ks < 4; ++ks) {
            uint32_t af2[2][4], bfr2[3][4];
            #pragma unroll
            for (int mt = 0; mt < 2; ++mt) {
                int mrow = wm * 32 + mt * 16 + (lane & 15);
                int c = (ks << 1) + (lane >> 4);
                ldm_x4(af2[mt], &sa[(mrow << 6) + ((c ^ (mrow & 7)) << 3)]);
            }
            #pragma unroll
            for (int ng = 0; ng < 3; ++ng) {
                int krow = (ks << 4) + (lane & 7) + ((lane >> 3) & 1) * 8;
                int nc = wn * 6 + ng * 2 + (lane >> 4);
                int sw = (nc & 8) | ((nc & 7) ^ (krow & 7));
                ldm_x4t(bfr2[ng], &sb[(krow << 7) + (sw << 3)]);
            }
            #pragma unroll
            for (int mt = 0; mt < 2; ++mt)
                #pragma unroll
                for (int ng = 0; ng < 3; ++ng) {
                    mma_bf16(acc[mt][ng * 2 + 0], af2[mt], &bfr2[ng][0]);
                    mma_bf16(acc[mt][ng * 2 + 1], af2[mt], &bfr2[ng][2]);
                }
        }
    }
    gemm_epilogue<EPI>(acc, bm, bn, wm, wn, lane, bias, outv, res, N);
}

// ---------------- HMMA window attention: one block per (window, head), 128 thr ----------------
__global__ void __launch_bounds__(128)
attn_kernel(const __nv_bfloat16* __restrict__ qkv, const __nv_bfloat16* __restrict__ bm,
            __nv_bfloat16* __restrict__ out) {
    __shared__ __align__(16) __nv_bfloat16 s[3][64 * 40];  // q, k, v (80B rows)
    const int wh = blockIdx.x;
    const int win = wh / 6, h = wh - win * 6;
    const long base = (long)wh * 1568;
    const int tid = threadIdx.x, lane = tid & 31, warp = tid >> 5;
    const int g = lane >> 2, t = lane & 3;

    // zero ONLY rows 49..63, cols 0..31 (cols 32..39 are never read; rows 0..48 overwritten)
    for (int i = tid; i < 720; i += 128) {       // 3 arrays * 15 rows * 16 u32
        int which = i / 240, r = i - which * 240;
        int row = 49 + (r >> 4), c = r & 15;
        ((uint32_t*)&s[which][row * 40])[c] = 0;
    }
    for (int i = tid; i < 588; i += 128) {
        int which = i / 196, r = i - which * 196;
        int row = r >> 2, c = r & 3;
        *(uint4*)&s[which][row * 40 + c * 8] =
            *(const uint4*)&qkv[(long)which * QKV_STRIDE + base + row * 32 + c * 8];
    }
    __syncthreads();

    // ---- S = Q K^T ----
    float sc[8][4];
    #pragma unroll
    for (int i = 0; i < 8; i++)
        #pragma unroll
        for (int j = 0; j < 4; j++) sc[i][j] = 0.f;
    uint32_t aq[2][4];
    #pragma unroll
    for (int ks = 0; ks < 2; ++ks) {
        int mrow = warp * 16 + (lane & 15);
        int c = ks * 2 + (lane >> 4);
        ldm_x4(aq[ks], &s[0][mrow * 40 + c * 8]);
    }
    #pragma unroll
    for (int nt2 = 0; nt2 < 4; ++nt2) {
        #pragma unroll
        for (int ks = 0; ks < 2; ++ks) {
            int row = nt2 * 16 + ((lane >> 3) >= 2 ? 8 : 0) + (lane & 7);
            int c = ks * 2 + ((lane >> 3) & 1);
            uint32_t kb[4];
            ldm_x4(kb, &s[1][row * 40 + c * 8]);
            mma_bf16(sc[nt2 * 2 + 0], aq[ks], &kb[0]);
            mma_bf16(sc[nt2 * 2 + 1], aq[ks], &kb[2]);
        }
    }

    // ---- bias+mask (bf16 padded table, branchless) + softmax (no max-sub) ----
    const int wloc = win & 63;
    const int typ = (((wloc >> 3) == 7) ? 2 : 0) + (((wloc & 7) == 7) ? 1 : 0);
    const __nv_bfloat16* __restrict__ bmp = bm + (typ * 6 + h) * (49 * 64);
    int n0 = warp * 16 + g, n1 = n0 + 8;
    int n0c = n0 < 49 ? n0 : 48, n1c = n1 < 49 ? n1 : 48;
    const __nv_bfloat16* bmp0 = bmp + n0c * 64;
    const __nv_bfloat16* bmp1 = bmp + n1c * 64;
    #pragma unroll
    for (int ng = 0; ng < 8; ++ng) {
        float2 b0 = __bfloat1622float2(*(const __nv_bfloat162*)&bmp0[ng * 8 + t * 2]);
        float2 b1 = __bfloat1622float2(*(const __nv_bfloat162*)&bmp1[ng * 8 + t * 2]);
        sc[ng][0] += b0.x; sc[ng][1] += b0.y;
        sc[ng][2] += b1.x; sc[ng][3] += b1.y;
    }
    float sum0 = 0.f, sum1 = 0.f;
    #pragma unroll
    for (int ng = 0; ng < 8; ++ng) {
        sc[ng][0] = __expf(sc[ng][0]); sum0 += sc[ng][0];
        sc[ng][1] = __expf(sc[ng][1]); sum0 += sc[ng][1];
        sc[ng][2] = __expf(sc[ng][2]); sum1 += sc[ng][2];
        sc[ng][3] = __expf(sc[ng][3]); sum1 += sc[ng][3];
    }
    sum0 += __shfl_xor_sync(0xffffffffu, sum0, 1);
    sum0 += __shfl_xor_sync(0xffffffffu, sum0, 2);
    sum1 += __shfl_xor_sync(0xffffffffu, sum1, 1);
    sum1 += __shfl_xor_sync(0xffffffffu, sum1, 2);
    float inv0 = 1.f / sum0, inv1 = 1.f / sum1;

    uint32_t pa[4][4];
    #pragma unroll
    for (int ks = 0; ks < 4; ++ks) {
        __nv_bfloat162 b2;
        b2 = __float22bfloat162_rn(make_float2(sc[2 * ks][0] * inv0, sc[2 * ks][1] * inv0));
        pa[ks][0] = *(uint32_t*)&b2;
        b2 = __float22bfloat162_rn(make_float2(sc[2 * ks][2] * inv1, sc[2 * ks][3] * inv1));
        pa[ks][1] = *(uint32_t*)&b2;
        b2 = __float22bfloat162_rn(make_float2(sc[2 * ks + 1][0] * inv0, sc[2 * ks + 1][1] * inv0));
        pa[ks][2] = *(uint32_t*)&b2;
        b2 = __float22bfloat162_rn(make_float2(sc[2 * ks + 1][2] * inv1, sc[2 * ks + 1][3] * inv1));
        pa[ks][3] = *(uint32_t*)&b2;
    }

    float oc[4][4];
    #pragma unroll
    for (int i = 0; i < 4; i++)
        #pragma unroll
        for (int j = 0; j < 4; j++) oc[i][j] = 0.f;
    #pragma unroll
    for (int ks = 0; ks < 4; ++ks) {
        #pragma unroll
        for (int ngv = 0; ngv < 2; ++ngv) {
            int row = ks * 16 + (lane & 7) + ((lane >> 3) & 1) * 8;
            int c = ngv * 2 + (lane >> 4);
            uint32_t vb[4];
            ldm_x4t(vb, &s[2][row * 40 + c * 8]);
            mma_bf16(oc[ngv * 2 + 0], pa[ks], &vb[0]);
            mma_bf16(oc[ngv * 2 + 1], pa[ks], &vb[2]);
        }
    }

    #pragma unroll
    for (int nt = 0; nt < 4; ++nt) {
        int d = nt * 8 + t * 2;
        if (n0 < 49) {
            __nv_bfloat162 v2 = __float22bfloat162_rn(make_float2(oc[nt][0], oc[nt][1]));
            *(__nv_bfloat162*)&out[((long)win * 49 + n0) * 192 + h * 32 + d] = v2;
        }
        if (n1 < 49) {
            __nv_bfloat162 v2 = __float22bfloat162_rn(make_float2(oc[nt][2], oc[nt][3]));
            *(__nv_bfloat162*)&out[((long)win * 49 + n1) * 192 + h * 32 + d] = v2;
        }
    }
}

// ---------------- launcher ----------------
extern "C" void kernel_launch(void* const* d_in, const int* in_sizes, int n_in,
                              void* d_out, int out_size) {
    const float* x      = (const float*)d_in[0];
    const float* gamma1 = (const float*)d_in[1];
    const float* beta1  = (const float*)d_in[2];
    const float* qkv_w  = (const float*)d_in[3];
    const float* qkv_b  = (const float*)d_in[4];
    const float* proj_w = (const float*)d_in[5];
    const float* proj_b = (const float*)d_in[6];
    const float* rel_tb = (const float*)d_in[7];
    const float* gamma2 = (const float*)d_in[8];
    const float* beta2  = (const float*)d_in[9];
    const float* fc1_w  = (const float*)d_in[10];
    const float* fc1_b  = (const float*)d_in[11];
    const float* fc2_w  = (const float*)d_in[12];
    const float* fc2_b  = (const float*)d_in[13];
    float* out = (float*)d_out;

    __nv_bfloat16 *abf, *qkvbf, *hbf, *wbf, *bmp;
    float *xr;
    cudaGetSymbolAddress((void**)&abf,   g_a_bf);
    cudaGetSymbolAddress((void**)&qkvbf, g_qkv_bf);
    cudaGetSymbolAddress((void**)&xr,    g_x);
    cudaGetSymbolAddress((void**)&hbf,   g_h_bf);
    cudaGetSymbolAddress((void**)&wbf,   g_w_bf);
    cudaGetSymbolAddress((void**)&bmp,   g_bm);

    __nv_bfloat16* wqkv  = wbf;                // [192][576]
    __nv_bfloat16* wproj = wbf + 110592;       // [192][192]
    __nv_bfloat16* wfc1  = wbf + 147456;       // [192][768]
    __nv_bfloat16* wfc2  = wbf + 294912;       // [768][192]

    const int fullk_smem = (128 * 192 + 192 * 128) * 2;  // 98304
    cudaFuncSetAttribute(gemm_fullk<EPI_QKV>,  cudaFuncAttributeMaxDynamicSharedMemorySize, fullk_smem);
    cudaFuncSetAttribute(gemm_fullk<EPI_GELU>, cudaFuncAttributeMaxDynamicSharedMemorySize, fullk_smem);
    const int projln_smem = (128 * 192 + 192 * 192) * 2 + 4096;  // 126976
    cudaFuncSetAttribute(gemm_proj_ln, cudaFuncAttributeMaxDynamicSharedMemorySize, projln_smem);
    const int fc2_smem = 3 * 16384 * 2;                  // 98304
    cudaFuncSetAttribute(gemm_bf16<EPI_RES>,   cudaFuncAttributeMaxDynamicSharedMemorySize, fc2_smem);

    prep_kernel<<<1752, 256>>>(qkv_w, proj_w, fc1_w, fc2_w, wbf, rel_tb, bmp);

    ln_kernel<true><<<12544, 256>>>(x, gamma1, beta1, abf);
    gemm_fullk<EPI_QKV><<<dim3(6, 784), 256, fullk_smem>>>(abf, wqkv, qkv_b, qkvbf, nullptr, TOKENS, 576);
    attn_kernel<<<12288, 128>>>(qkvbf, bmp, abf);
    gemm_proj_ln<<<784, 512, projln_smem>>>(abf, wproj, proj_b, xr, x, gamma2, beta2, qkvbf);
    gemm_fullk<EPI_GELU><<<dim3(8, 784), 256, fullk_smem>>>(qkvbf, wfc1, fc1_b, hbf, nullptr, TOKENS, 768);
    gemm_bf16<EPI_RES><<<dim3(2, 784), 256, fc2_smem>>>(hbf, wfc2, fc2_b, out, xr, TOKENS, 192, 768);
}

// round 14
// speedup vs baseline: 1.0626x; 1.0626x over previous
#include <cuda_runtime.h>
#include <cuda_bf16.h>
#include <math.h>
#include <stdint.h>

// ---------------- problem constants ----------------
static constexpr int TOKENS = 100352;          // B*L
static constexpr long QKV_STRIDE = 19267584L;  // TOKENS*192
static constexpr float QSCALE = 0.17677669529663687f; // 32^-0.5

// ---------------- scratch (device globals; no allocation) ----------------
__device__ __nv_bfloat16 g_a_bf[19267584];    // LN1 out (window order) -> reused as attn out
__device__ __nv_bfloat16 g_qkv_bf[57802752];  // qkv ; first third reused as LN2 out
__device__ float         g_x[19267584];       // x after attention residual (fp32)
__device__ __nv_bfloat16 g_h_bf[77070336];    // fc1/gelu output (TOKENS*768)
__device__ __nv_bfloat16 g_w_bf[442368];      // bf16 weights row-major [K,N]: qkv|proj|fc1|fc2
__device__ __nv_bfloat16 g_bm[75264];         // bias+mask bf16: 4 wtypes x 6 heads x 49 x 64

// ---------------- prep: weight convert + padded bf16 bias/mask table ----------------
__global__ void prep_kernel(const float* __restrict__ w0, const float* __restrict__ w1,
                            const float* __restrict__ w2, const float* __restrict__ w3,
                            __nv_bfloat16* __restrict__ d,
                            const float* __restrict__ table, __nv_bfloat16* __restrict__ bm) {
    if (blockIdx.x < 1728) {
        int i = blockIdx.x * 256 + threadIdx.x;
        if (i >= 442368) return;
        float v;
        if (i < 110592) v = w0[i];
        else if (i < 147456) v = w1[i - 110592];
        else if (i < 294912) v = w2[i - 147456];
        else v = w3[i - 294912];
        d[i] = __float2bfloat16(v);
    } else {
        int th = blockIdx.x - 1728;
        int typ = th / 6, h = th - typ * 6;
        int wrow = (typ & 2) ? 49 : 0, wcol = (typ & 1) ? 49 : 0;
        for (int e = threadIdx.x; e < 49 * 64; e += 256) {
            int n = e >> 6, m = e & 63;
            float v;
            if (m < 49) {
                int ni = n / 7, nj = n - ni * 7, mi = m / 7, mj = m - mi * 7;
                v = table[((ni - mi + 6) * 13 + (nj - mj + 6)) * 6 + h];
                int rn = wrow + ni, cn = wcol + nj, rm = wrow + mi, cm = wcol + mj;
                int idn = (rn < 49 ? 0 : (rn < 53 ? 1 : 2)) * 3 + (cn < 49 ? 0 : (cn < 53 ? 1 : 2));
                int idm = (rm < 49 ? 0 : (rm < 53 ? 1 : 2)) * 3 + (cm < 49 ? 0 : (cm < 53 ? 1 : 2));
                if (idn != idm) v -= 100.0f;
            } else {
                v = -1e9f;
            }
            bm[th * (49 * 64) + e] = __float2bfloat16(v);
        }
    }
}

// ---------------- LayerNorm, warp-per-row (8 rows/block), float2/bf162 ----------------
template<bool REMAP>
__global__ void __launch_bounds__(256)
ln_kernel(const float* __restrict__ x, const float* __restrict__ gamma,
          const float* __restrict__ beta, __nv_bfloat16* __restrict__ out) {
    const int warp = threadIdx.x >> 5, lane = threadIdx.x & 31;
    const int g = blockIdx.x * 8 + warp;
    long src;
    if (REMAP) {
        int gw = g / 49, n = g - gw * 49;
        int b = gw >> 6, wloc = gw & 63;
        int hp = (wloc >> 3) * 7 + n / 7;
        int wp = (wloc & 7) * 7 + n % 7;
        int hh = hp + 3; if (hh >= 56) hh -= 56;
        int ww = wp + 3; if (ww >= 56) ww -= 56;
        src = ((long)b * 3136 + hh * 56 + ww) * 192;
    } else {
        src = (long)g * 192;
    }
    float2 v[3];
    float s1 = 0.f, s2 = 0.f;
    #pragma unroll
    for (int i = 0; i < 3; i++) {
        v[i] = *(const float2*)&x[src + i * 64 + lane * 2];
        s1 += v[i].x + v[i].y;
        s2 += v[i].x * v[i].x + v[i].y * v[i].y;
    }
    #pragma unroll
    for (int o = 16; o; o >>= 1) {
        s1 += __shfl_xor_sync(0xffffffffu, s1, o);
        s2 += __shfl_xor_sync(0xffffffffu, s2, o);
    }
    float mean = s1 * (1.f / 192.f);
    float var = s2 * (1.f / 192.f) - mean * mean;
    float rstd = rsqrtf(var + 1e-3f);
    #pragma unroll
    for (int i = 0; i < 3; i++) {
        int c = i * 64 + lane * 2;
        float2 gm = *(const float2*)&gamma[c];
        float2 bt = *(const float2*)&beta[c];
        __nv_bfloat162 p = __float22bfloat162_rn(make_float2(
            (v[i].x - mean) * rstd * gm.x + bt.x,
            (v[i].y - mean) * rstd * gm.y + bt.y));
        *(__nv_bfloat162*)&out[(long)g * 192 + c] = p;
    }
}

// ---------------- mma / ldmatrix helpers ----------------
__device__ __forceinline__ void cpa16(void* sm, const void* gm) {
    uint32_t sa = (uint32_t)__cvta_generic_to_shared(sm);
    asm volatile("cp.async.cg.shared.global [%0], [%1], 16;" :: "r"(sa), "l"(gm));
}
__device__ __forceinline__ void mma_bf16(float* d, const uint32_t* a, const uint32_t* b) {
    asm volatile(
        "mma.sync.aligned.m16n8k16.row.col.f32.bf16.bf16.f32 "
        "{%0,%1,%2,%3}, {%4,%5,%6,%7}, {%8,%9}, {%0,%1,%2,%3};"
        : "+f"(d[0]), "+f"(d[1]), "+f"(d[2]), "+f"(d[3])
        : "r"(a[0]), "r"(a[1]), "r"(a[2]), "r"(a[3]), "r"(b[0]), "r"(b[1]));
}
__device__ __forceinline__ void ldm_x4(uint32_t* r, const void* p) {
    uint32_t sa = (uint32_t)__cvta_generic_to_shared(p);
    asm volatile("ldmatrix.sync.aligned.m8n8.x4.shared.b16 {%0,%1,%2,%3}, [%4];"
                 : "=r"(r[0]), "=r"(r[1]), "=r"(r[2]), "=r"(r[3]) : "r"(sa));
}
__device__ __forceinline__ void ldm_x4t(uint32_t* r, const void* p) {
    uint32_t sa = (uint32_t)__cvta_generic_to_shared(p);
    asm volatile("ldmatrix.sync.aligned.m8n8.x4.trans.shared.b16 {%0,%1,%2,%3}, [%4];"
                 : "=r"(r[0]), "=r"(r[1]), "=r"(r[2]), "=r"(r[3]) : "r"(sa));
}

// ---------------- shared GEMM epilogue (paired stores) ----------------
enum { EPI_QKV = 0, EPI_PROJ = 1, EPI_GELU = 2, EPI_RES = 3 };

template<int EPI>
__device__ __forceinline__ void gemm_epilogue(
    float acc[2][6][4], int bm, int bn, int wm, int wn, int lane,
    const float* __restrict__ bias, void* __restrict__ outv,
    const float* __restrict__ res, int N) {
    const int g = lane >> 2, t = lane & 3;
    #pragma unroll
    for (int mt = 0; mt < 2; ++mt)
        #pragma unroll
        for (int rr = 0; rr < 2; ++rr) {
            const int row = bm + wm * 32 + mt * 16 + rr * 8 + g;
            int win = 0, n = 0;
            long tmap = 0;
            if (EPI == EPI_QKV || EPI == EPI_PROJ) { win = row / 49; n = row - win * 49; }
            if (EPI == EPI_PROJ) {
                int b = win >> 6, wloc = win & 63;
                int hp = (wloc >> 3) * 7 + n / 7, wp = (wloc & 7) * 7 + n % 7;
                int hh = hp + 3; if (hh >= 56) hh -= 56;
                int ww = wp + 3; if (ww >= 56) ww -= 56;
                tmap = ((long)b * 3136 + hh * 56 + ww) * 192;
            }
            #pragma unroll
            for (int nt = 0; nt < 6; ++nt) {
                const int col = bn + wn * 48 + nt * 8 + t * 2;
                float v0 = acc[mt][nt][rr * 2 + 0] + bias[col];
                float v1 = acc[mt][nt][rr * 2 + 1] + bias[col + 1];
                if (EPI == EPI_QKV) {
                    int which = col / 192;
                    int rem = col - which * 192;
                    int h = rem >> 5, d = rem & 31;
                    if (which == 0) { v0 *= QSCALE; v1 *= QSCALE; }
                    __nv_bfloat162 p = __float22bfloat162_rn(make_float2(v0, v1));
                    *(__nv_bfloat162*)&((__nv_bfloat16*)outv)[(long)which * QKV_STRIDE +
                        (((long)win * 6 + h) * 49 + n) * 32 + d] = p;
                } else if (EPI == EPI_PROJ) {
                    long ti = tmap + col;
                    float2 r2 = *(const float2*)&res[ti];
                    *(float2*)&((float*)outv)[ti] = make_float2(r2.x + v0, r2.y + v1);
                } else if (EPI == EPI_GELU) {
                    float u0 = 0.7978845608028654f * (v0 + 0.044715f * v0 * v0 * v0);
                    float u1 = 0.7978845608028654f * (v1 + 0.044715f * v1 * v1 * v1);
                    float t0, t1;
                    asm("tanh.approx.f32 %0, %1;" : "=f"(t0) : "f"(u0));
                    asm("tanh.approx.f32 %0, %1;" : "=f"(t1) : "f"(u1));
                    __nv_bfloat162 p = __float22bfloat162_rn(
                        make_float2(0.5f * v0 * (1.f + t0), 0.5f * v1 * (1.f + t1)));
                    *(__nv_bfloat162*)&((__nv_bfloat16*)outv)[(long)row * N + col] = p;
                } else {  // EPI_RES
                    long idx2 = (long)row * N + col;
                    float2 r2 = *(const float2*)&res[idx2];
                    *(float2*)&((float*)outv)[idx2] = make_float2(r2.x + v0, r2.y + v1);
                }
            }
        }
}

// ---------------- full-K-resident GEMM (K=192), chunked-load overlap (R7 body) ----------------
template<int EPI>
__global__ void __launch_bounds__(256, 2)
gemm_fullk(const __nv_bfloat16* __restrict__ A, const __nv_bfloat16* __restrict__ W,
           const float* __restrict__ bias, void* __restrict__ outv,
           const float* __restrict__ res, int M, int N) {
    extern __shared__ __align__(16) __nv_bfloat16 smem[];
    __nv_bfloat16* sA = smem;               // 128 x 192 (swizzled per 64-col group)
    __nv_bfloat16* sB = smem + 128 * 192;   // 192 x 128 (cols padded; 96 used)
    const int tid = threadIdx.x, lane = tid & 31, warp = tid >> 5;
    const int wm = warp >> 1, wn = warp & 1;
    const int bm = blockIdx.y * 128, bn = blockIdx.x * 96;

    #pragma unroll
    for (int gch = 0; gch < 3; ++gch) {
        #pragma unroll
        for (int i = 0; i < 4; i++) {
            int idx = i * 256 + tid, r = idx >> 3, cc = idx & 7;
            cpa16(&sA[r * 192 + gch * 64 + ((cc ^ (r & 7)) << 3)],
                  A + (long)(bm + r) * 192 + gch * 64 + cc * 8);
        }
        #pragma unroll
        for (int i = 0; i < 3; i++) {
            int idx = i * 256 + tid, rl = idx / 12, c = idx % 12;
            int r = gch * 64 + rl;
            cpa16(&sB[r * 128 + (((c & 8) | ((c & 7) ^ (r & 7))) << 3)],
                  W + (long)r * N + bn + c * 8);
        }
        asm volatile("cp.async.commit_group;");
    }

    float acc[2][6][4];
    #pragma unroll
    for (int i = 0; i < 2; i++)
        #pragma unroll
        for (int j = 0; j < 6; j++)
            #pragma unroll
            for (int e = 0; e < 4; e++) acc[i][j][e] = 0.f;

    #pragma unroll
    for (int gch = 0; gch < 3; ++gch) {
        if (gch == 0)      asm volatile("cp.async.wait_group 2;");
        else if (gch == 1) asm volatile("cp.async.wait_group 1;");
        else               asm volatile("cp.async.wait_group 0;");
        __syncthreads();
        #pragma unroll
        for (int kk = 0; kk < 4; ++kk) {
            const int ks = gch * 4 + kk;
            uint32_t af[2][4], bfr[3][4];
            #pragma unroll
            for (int mt = 0; mt < 2; ++mt) {
                int mrow = wm * 32 + mt * 16 + (lane & 15);
                int c = (ks << 1) + (lane >> 4);
                ldm_x4(af[mt], &sA[mrow * 192 + (c >> 3) * 64 + (((c & 7) ^ (mrow & 7)) << 3)]);
            }
            #pragma unroll
            for (int ng = 0; ng < 3; ++ng) {
                int krow = (ks << 4) + (lane & 7) + ((lane >> 3) & 1) * 8;
                int nc = wn * 6 + ng * 2 + (lane >> 4);
                int sw = (nc & 8) | ((nc & 7) ^ (krow & 7));
                ldm_x4t(bfr[ng], &sB[krow * 128 + (sw << 3)]);
            }
            #pragma unroll
            for (int mt = 0; mt < 2; ++mt)
                #pragma unroll
                for (int ng = 0; ng < 3; ++ng) {
                    mma_bf16(acc[mt][ng * 2 + 0], af[mt], &bfr[ng][0]);
                    mma_bf16(acc[mt][ng * 2 + 1], af[mt], &bfr[ng][2]);
                }
        }
    }
    gemm_epilogue<EPI>(acc, bm, bn, wm, wn, lane, bias, outv, res, N);
}

// ---------------- pipelined GEMM (K=768, FC2): 3-stage, one barrier per K-step ----------------
template<int EPI>
__global__ void __launch_bounds__(256, 2)
gemm_bf16(const __nv_bfloat16* __restrict__ A, const __nv_bfloat16* __restrict__ W,
          const float* __restrict__ bias, void* __restrict__ outv,
          const float* __restrict__ res, int M, int N, int K) {
    extern __shared__ __align__(16) __nv_bfloat16 smem[];
    const int tid = threadIdx.x, lane = tid & 31, warp = tid >> 5;
    const int wm = warp >> 1, wn = warp & 1;
    const int bm = blockIdx.y * 128, bn = blockIdx.x * 96;

    float acc[2][6][4];
    #pragma unroll
    for (int i = 0; i < 2; i++)
        #pragma unroll
        for (int j = 0; j < 6; j++)
            #pragma unroll
            for (int e = 0; e < 4; e++) acc[i][j][e] = 0.f;

    const int nstages = K >> 6;   // 12

    #define LOAD_STAGE(s, k0)                                                          \
        {                                                                              \
            __nv_bfloat16* sa = smem + (s) * 16384;                                    \
            __nv_bfloat16* sb = sa + 8192;                                             \
            _Pragma("unroll")                                                          \
            for (int i = 0; i < 4; i++) {                                              \
                int idx = tid + i * 256, row = idx >> 3, c = idx & 7;                  \
                cpa16(&sa[(row << 6) + ((c ^ (row & 7)) << 3)],                        \
                      A + (long)(bm + row) * K + (k0) + (c << 3));                     \
            }                                                                          \
            _Pragma("unroll")                                                          \
            for (int i = 0; i < 4; i++) {                                              \
                int idx = tid + i * 256, row = idx >> 4, c = idx & 15;                 \
                if (c < 12)                                                            \
                    cpa16(&sb[(row << 7) + (((c & 8) | ((c & 7) ^ (row & 7))) << 3)],  \
                          W + (long)((k0) + row) * N + bn + (c << 3));                 \
            }                                                                          \
            asm volatile("cp.async.commit_group;");                                    \
        }

    LOAD_STAGE(0, 0)
    LOAD_STAGE(1, 64)

    for (int it = 0; it < nstages; ++it) {
        if (it + 2 < nstages) {
            asm volatile("cp.async.wait_group 1;");
        } else {
            asm volatile("cp.async.wait_group 0;");
        }
        __syncthreads();
        if (it + 2 < nstages) {
            int s2 = (it + 2) % 3;
            LOAD_STAGE(s2, (it + 2) << 6)
        }
        const __nv_bfloat16* sa = smem + (it % 3) * 16384;
        const __nv_bfloat16* sb = sa + 8192;
        #pragma unroll
        for (int ks = 0; ks < 4; ++ks) {
            uint32_t af2[2][4], bfr2[3][4];
            #pragma unroll
            for (int mt = 0; mt < 2; ++mt) {
                int mrow = wm * 32 + mt * 16 + (lane & 15);
                int c = (ks << 1) + (lane >> 4);
                ldm_x4(af2[mt], &sa[(mrow << 6) + ((c ^ (mrow & 7)) << 3)]);
            }
            #pragma unroll
            for (int ng = 0; ng < 3; ++ng) {
                int krow = (ks << 4) + (lane & 7) + ((lane >> 3) & 1) * 8;
                int nc = wn * 6 + ng * 2 + (lane >> 4);
                int sw = (nc & 8) | ((nc & 7) ^ (krow & 7));
                ldm_x4t(bfr2[ng], &sb[(krow << 7) + (sw << 3)]);
            }
            #pragma unroll
            for (int mt = 0; mt < 2; ++mt)
                #pragma unroll
                for (int ng = 0; ng < 3; ++ng) {
                    mma_bf16(acc[mt][ng * 2 + 0], af2[mt], &bfr2[ng][0]);
                    mma_bf16(acc[mt][ng * 2 + 1], af2[mt], &bfr2[ng][2]);
                }
        }
    }
    gemm_epilogue<EPI>(acc, bm, bn, wm, wn, lane, bias, outv, res, N);
}

// ---------------- HMMA window attention: one block per (window, head), 128 thr ----------------
// Loads q/k/v via cp.async (L2->smem, bypasses L1 + register round-trip).
__global__ void __launch_bounds__(128)
attn_kernel(const __nv_bfloat16* __restrict__ qkv, const __nv_bfloat16* __restrict__ bm,
            __nv_bfloat16* __restrict__ out) {
    __shared__ __align__(16) __nv_bfloat16 s[3][64 * 40];  // q, k, v (80B rows)
    const int wh = blockIdx.x;
    const int win = wh / 6, h = wh - win * 6;
    const long base = (long)wh * 1568;
    const int tid = threadIdx.x, lane = tid & 31, warp = tid >> 5;
    const int g = lane >> 2, t = lane & 3;

    // issue cp.async loads for rows 0..48 (cols 0..31), disjoint from pad rows
    for (int i = tid; i < 588; i += 128) {
        int which = i / 196, r = i - which * 196;
        int row = r >> 2, c = r & 3;
        cpa16(&s[which][row * 40 + c * 8],
              &qkv[(long)which * QKV_STRIDE + base + row * 32 + c * 8]);
    }
    asm volatile("cp.async.commit_group;");
    // zero pad rows 49..63, cols 0..39 (20 u32 per row) while loads are in flight
    for (int i = tid; i < 900; i += 128) {
        int which = i / 300, r = i - which * 300;
        ((uint32_t*)&s[which][(49 + r / 20) * 40])[r % 20] = 0;
    }
    asm volatile("cp.async.wait_group 0;");
    __syncthreads();

    // ---- S = Q K^T ----
    float sc[8][4];
    #pragma unroll
    for (int i = 0; i < 8; i++)
        #pragma unroll
        for (int j = 0; j < 4; j++) sc[i][j] = 0.f;
    uint32_t aq[2][4];
    #pragma unroll
    for (int ks = 0; ks < 2; ++ks) {
        int mrow = warp * 16 + (lane & 15);
        int c = ks * 2 + (lane >> 4);
        ldm_x4(aq[ks], &s[0][mrow * 40 + c * 8]);
    }
    #pragma unroll
    for (int nt2 = 0; nt2 < 4; ++nt2) {
        #pragma unroll
        for (int ks = 0; ks < 2; ++ks) {
            int row = nt2 * 16 + ((lane >> 3) >= 2 ? 8 : 0) + (lane & 7);
            int c = ks * 2 + ((lane >> 3) & 1);
            uint32_t kb[4];
            ldm_x4(kb, &s[1][row * 40 + c * 8]);
            mma_bf16(sc[nt2 * 2 + 0], aq[ks], &kb[0]);
            mma_bf16(sc[nt2 * 2 + 1], aq[ks], &kb[2]);
        }
    }

    // ---- bias+mask (bf16 padded table, branchless) + softmax (no max-sub) ----
    const int wloc = win & 63;
    const int typ = (((wloc >> 3) == 7) ? 2 : 0) + (((wloc & 7) == 7) ? 1 : 0);
    const __nv_bfloat16* __restrict__ bmp = bm + (typ * 6 + h) * (49 * 64);
    int n0 = warp * 16 + g, n1 = n0 + 8;
    int n0c = n0 < 49 ? n0 : 48, n1c = n1 < 49 ? n1 : 48;
    const __nv_bfloat16* bmp0 = bmp + n0c * 64;
    const __nv_bfloat16* bmp1 = bmp + n1c * 64;
    #pragma unroll
    for (int ng = 0; ng < 8; ++ng) {
        float2 b0 = __bfloat1622float2(*(const __nv_bfloat162*)&bmp0[ng * 8 + t * 2]);
        float2 b1 = __bfloat1622float2(*(const __nv_bfloat162*)&bmp1[ng * 8 + t * 2]);
        sc[ng][0] += b0.x; sc[ng][1] += b0.y;
        sc[ng][2] += b1.x; sc[ng][3] += b1.y;
    }
    float sum0 = 0.f, sum1 = 0.f;
    #pragma unroll
    for (int ng = 0; ng < 8; ++ng) {
        sc[ng][0] = __expf(sc[ng][0]); sum0 += sc[ng][0];
        sc[ng][1] = __expf(sc[ng][1]); sum0 += sc[ng][1];
        sc[ng][2] = __expf(sc[ng][2]); sum1 += sc[ng][2];
        sc[ng][3] = __expf(sc[ng][3]); sum1 += sc[ng][3];
    }
    sum0 += __shfl_xor_sync(0xffffffffu, sum0, 1);
    sum0 += __shfl_xor_sync(0xffffffffu, sum0, 2);
    sum1 += __shfl_xor_sync(0xffffffffu, sum1, 1);
    sum1 += __shfl_xor_sync(0xffffffffu, sum1, 2);
    float inv0 = 1.f / sum0, inv1 = 1.f / sum1;

    uint32_t pa[4][4];
    #pragma unroll
    for (int ks = 0; ks < 4; ++ks) {
        __nv_bfloat162 b2;
        b2 = __float22bfloat162_rn(make_float2(sc[2 * ks][0] * inv0, sc[2 * ks][1] * inv0));
        pa[ks][0] = *(uint32_t*)&b2;
        b2 = __float22bfloat162_rn(make_float2(sc[2 * ks][2] * inv1, sc[2 * ks][3] * inv1));
        pa[ks][1] = *(uint32_t*)&b2;
        b2 = __float22bfloat162_rn(make_float2(sc[2 * ks + 1][0] * inv0, sc[2 * ks + 1][1] * inv0));
        pa[ks][2] = *(uint32_t*)&b2;
        b2 = __float22bfloat162_rn(make_float2(sc[2 * ks + 1][2] * inv1, sc[2 * ks + 1][3] * inv1));
        pa[ks][3] = *(uint32_t*)&b2;
    }

    float oc[4][4];
    #pragma unroll
    for (int i = 0; i < 4; i++)
        #pragma unroll
        for (int j = 0; j < 4; j++) oc[i][j] = 0.f;
    #pragma unroll
    for (int ks = 0; ks < 4; ++ks) {
        #pragma unroll
        for (int ngv = 0; ngv < 2; ++ngv) {
            int row = ks * 16 + (lane & 7) + ((lane >> 3) & 1) * 8;
            int c = ngv * 2 + (lane >> 4);
            uint32_t vb[4];
            ldm_x4t(vb, &s[2][row * 40 + c * 8]);
            mma_bf16(oc[ngv * 2 + 0], pa[ks], &vb[0]);
            mma_bf16(oc[ngv * 2 + 1], pa[ks], &vb[2]);
        }
    }

    #pragma unroll
    for (int nt = 0; nt < 4; ++nt) {
        int d = nt * 8 + t * 2;
        if (n0 < 49) {
            __nv_bfloat162 v2 = __float22bfloat162_rn(make_float2(oc[nt][0], oc[nt][1]));
            *(__nv_bfloat162*)&out[((long)win * 49 + n0) * 192 + h * 32 + d] = v2;
        }
        if (n1 < 49) {
            __nv_bfloat162 v2 = __float22bfloat162_rn(make_float2(oc[nt][2], oc[nt][3]));
            *(__nv_bfloat162*)&out[((long)win * 49 + n1) * 192 + h * 32 + d] = v2;
        }
    }
}

// ---------------- launcher ----------------
extern "C" void kernel_launch(void* const* d_in, const int* in_sizes, int n_in,
                              void* d_out, int out_size) {
    const float* x      = (const float*)d_in[0];
    const float* gamma1 = (const float*)d_in[1];
    const float* beta1  = (const float*)d_in[2];
    const float* qkv_w  = (const float*)d_in[3];
    const float* qkv_b  = (const float*)d_in[4];
    const float* proj_w = (const float*)d_in[5];
    const float* proj_b = (const float*)d_in[6];
    const float* rel_tb = (const float*)d_in[7];
    const float* gamma2 = (const float*)d_in[8];
    const float* beta2  = (const float*)d_in[9];
    const float* fc1_w  = (const float*)d_in[10];
    const float* fc1_b  = (const float*)d_in[11];
    const float* fc2_w  = (const float*)d_in[12];
    const float* fc2_b  = (const float*)d_in[13];
    float* out = (float*)d_out;

    __nv_bfloat16 *abf, *qkvbf, *hbf, *wbf, *bmp;
    float *xr;
    cudaGetSymbolAddress((void**)&abf,   g_a_bf);
    cudaGetSymbolAddress((void**)&qkvbf, g_qkv_bf);
    cudaGetSymbolAddress((void**)&xr,    g_x);
    cudaGetSymbolAddress((void**)&hbf,   g_h_bf);
    cudaGetSymbolAddress((void**)&wbf,   g_w_bf);
    cudaGetSymbolAddress((void**)&bmp,   g_bm);

    __nv_bfloat16* wqkv  = wbf;                // [192][576]
    __nv_bfloat16* wproj = wbf + 110592;       // [192][192]
    __nv_bfloat16* wfc1  = wbf + 147456;       // [192][768]
    __nv_bfloat16* wfc2  = wbf + 294912;       // [768][192]

    const int fullk_smem = (128 * 192 + 192 * 128) * 2;  // 98304 bytes
    cudaFuncSetAttribute(gemm_fullk<EPI_QKV>,  cudaFuncAttributeMaxDynamicSharedMemorySize, fullk_smem);
    cudaFuncSetAttribute(gemm_fullk<EPI_PROJ>, cudaFuncAttributeMaxDynamicSharedMemorySize, fullk_smem);
    cudaFuncSetAttribute(gemm_fullk<EPI_GELU>, cudaFuncAttributeMaxDynamicSharedMemorySize, fullk_smem);
    const int fc2_smem = 3 * 16384 * 2;                  // 98304 bytes (3 stages)
    cudaFuncSetAttribute(gemm_bf16<EPI_RES>,   cudaFuncAttributeMaxDynamicSharedMemorySize, fc2_smem);

    prep_kernel<<<1752, 256>>>(qkv_w, proj_w, fc1_w, fc2_w, wbf, rel_tb, bmp);

    ln_kernel<true><<<12544, 256>>>(x, gamma1, beta1, abf);
    gemm_fullk<EPI_QKV><<<dim3(6, 784), 256, fullk_smem>>>(abf, wqkv, qkv_b, qkvbf, nullptr, TOKENS, 576);
    attn_kernel<<<12288, 128>>>(qkvbf, bmp, abf);
    gemm_fullk<EPI_PROJ><<<dim3(2, 784), 256, fullk_smem>>>(abf, wproj, proj_b, xr, x, TOKENS, 192);
    ln_kernel<false><<<12544, 256>>>(xr, gamma2, beta2, qkvbf);
    gemm_fullk<EPI_GELU><<<dim3(8, 784), 256, fullk_smem>>>(qkvbf, wfc1, fc1_b, hbf, nullptr, TOKENS, 768);
    gemm_bf16<EPI_RES><<<dim3(2, 784), 256, fc2_smem>>>(hbf, wfc2, fc2_b, out, xr, TOKENS, 192, 768);
}